// round 9
// baseline (speedup 1.0000x reference)
#include <cuda_runtime.h>
#include <cuda_bf16.h>
#include <cstdint>

#define NN 16384
#define DH 128
#define TT 256
#define QSCALE (0.08838834764831845f * 1.4426950408889634f)  // 1/sqrt(128) * log2(e)

#define BM 64
#define BN 128
#define NT (NN / BN)

// smem layout (bytes)
#define KS_STRIDE 272                      // 128 bf16 + 16B pad
#define HS_STRIDE 528                      // 256 bf16 + 16B pad
#define PS_STRIDE 272                      // Q staging stride (prologue only)
#define PB_STRIDE 144                      // P row: 64 keys bf16 + 16B pad
#define PBUF 9216                          // 64 * 144
#define KBYTES (128 * KS_STRIDE)           // 34816
#define HBYTES (128 * HS_STRIDE)           // 67584
#define OFF_K 0                            // 2 stages
#define OFF_H (2 * KBYTES)                 // 69632, 2 stages
#define OFF_P (OFF_H + 2 * HBYTES)         // 204800: 2 P bufs (18432B); Q staging prologue
#define OFF_L (OFF_P + 2 * PBUF)           // 223232
#define ATTN_SMEM (OFF_L + 4 * 64 * 4)     // 224256

// device-global scratch (allocation-guard safe)
__device__ __nv_bfloat16 g_Qb[NN * DH];          // Q*QSCALE bf16
__device__ __nv_bfloat16 g_Kb[NN * DH];          // K bf16
__device__ __nv_bfloat16 g_Hb[(size_t)NN * TT];  // H bf16

// ===========================================================================
// helpers (sm_80-baseline PTX: portable under compute_103)
// ===========================================================================
__device__ __forceinline__ uint32_t smem_u32(const void* p) {
    uint32_t a;
    asm("{ .reg .u64 t; cvta.to.shared.u64 t, %1; cvt.u32.u64 %0, t; }"
        : "=r"(a) : "l"(p));
    return a;
}
__device__ __forceinline__ void ldsm_x4(uint32_t& r0, uint32_t& r1,
                                        uint32_t& r2, uint32_t& r3, uint32_t a) {
    asm volatile("ldmatrix.sync.aligned.m8n8.x4.shared.b16 {%0,%1,%2,%3}, [%4];"
                 : "=r"(r0), "=r"(r1), "=r"(r2), "=r"(r3) : "r"(a));
}
__device__ __forceinline__ void ldsm_x4_t(uint32_t& r0, uint32_t& r1,
                                          uint32_t& r2, uint32_t& r3, uint32_t a) {
    asm volatile("ldmatrix.sync.aligned.m8n8.x4.trans.shared.b16 {%0,%1,%2,%3}, [%4];"
                 : "=r"(r0), "=r"(r1), "=r"(r2), "=r"(r3) : "r"(a));
}
__device__ __forceinline__ void mma16816(float* d, const uint32_t* a,
                                         uint32_t b0, uint32_t b1) {
    asm volatile("mma.sync.aligned.m16n8k16.row.col.f32.bf16.bf16.f32 "
                 "{%0,%1,%2,%3},{%4,%5,%6,%7},{%8,%9},{%0,%1,%2,%3};"
                 : "+f"(d[0]), "+f"(d[1]), "+f"(d[2]), "+f"(d[3])
                 : "r"(a[0]), "r"(a[1]), "r"(a[2]), "r"(a[3]), "r"(b0), "r"(b1));
}
__device__ __forceinline__ void cp16(uint32_t dst, const void* src) {
    asm volatile("cp.async.cg.shared.global [%0], [%1], 16;"
                 :: "r"(dst), "l"(src) : "memory");
}
__device__ __forceinline__ void cp_commit() {
    asm volatile("cp.async.commit_group;" ::: "memory");
}
__device__ __forceinline__ void cp_wait0() {
    asm volatile("cp.async.wait_group 0;" ::: "memory");
}
__device__ __forceinline__ float ex2f(float x) {
    float y;
    asm("ex2.approx.f32 %0, %1;" : "=f"(y) : "f"(x));
    return y;
}
__device__ __forceinline__ uint32_t packbf2(float lo, float hi) {
    __nv_bfloat162 v = __floats2bfloat162_rn(lo, hi);
    return *(uint32_t*)&v;
}

// ===========================================================================
// Kernel 1: Q = (H Wq + bq)*QSCALE -> bf16 ; K = H Wk + bk -> bf16 (2 CTA/SM)
// ===========================================================================
__global__ void __launch_bounds__(256, 2)
qk_kernel(const float* __restrict__ H,
          const float* __restrict__ Wq, const float* __restrict__ bq,
          const float* __restrict__ Wk, const float* __restrict__ bk) {
    __shared__ float HsT[32 * 129];
    __shared__ float Ws[32 * 128];

    const float* W = blockIdx.y ? Wk : Wq;
    const float* b = blockIdx.y ? bk : bq;
    __nv_bfloat16* outp = blockIdx.y ? g_Kb : g_Qb;
    const float osc = blockIdx.y ? 1.0f : QSCALE;

    const int tid = threadIdx.x;
    const int ty = tid >> 4, tx = tid & 15;
    const int row0 = blockIdx.x * 128;

    float acc[8][8];
    #pragma unroll
    for (int i = 0; i < 8; i++)
        #pragma unroll
        for (int j = 0; j < 8; j++) acc[i][j] = 0.f;

    for (int kc = 0; kc < TT; kc += 32) {
        __syncthreads();
        #pragma unroll
        for (int idx = tid; idx < 128 * 32; idx += 256) {
            int r = idx >> 5, k = idx & 31;
            HsT[k * 129 + r] = H[(size_t)(row0 + r) * TT + kc + k];
        }
        #pragma unroll
        for (int idx = tid; idx < 32 * 128; idx += 256) {
            int k = idx >> 7, c = idx & 127;
            Ws[k * 128 + c] = W[(size_t)(kc + k) * DH + c];
        }
        __syncthreads();
        #pragma unroll 4
        for (int k = 0; k < 32; k++) {
            float h[8], w[8];
            #pragma unroll
            for (int i = 0; i < 8; i++) h[i] = HsT[k * 129 + ty * 8 + i];
            float4 w0 = *(const float4*)&Ws[k * 128 + tx * 8];
            float4 w1 = *(const float4*)&Ws[k * 128 + tx * 8 + 4];
            w[0]=w0.x; w[1]=w0.y; w[2]=w0.z; w[3]=w0.w;
            w[4]=w1.x; w[5]=w1.y; w[6]=w1.z; w[7]=w1.w;
            #pragma unroll
            for (int i = 0; i < 8; i++)
                #pragma unroll
                for (int j = 0; j < 8; j++)
                    acc[i][j] += h[i] * w[j];
        }
    }

    float bb[8];
    {
        float4 b0 = *(const float4*)&b[tx * 8];
        float4 b1 = *(const float4*)&b[tx * 8 + 4];
        bb[0]=b0.x; bb[1]=b0.y; bb[2]=b0.z; bb[3]=b0.w;
        bb[4]=b1.x; bb[5]=b1.y; bb[6]=b1.z; bb[7]=b1.w;
    }
    #pragma unroll
    for (int i = 0; i < 8; i++) {
        int r = row0 + ty * 8 + i;
        __nv_bfloat16 t8[8];
        #pragma unroll
        for (int j = 0; j < 8; j++)
            t8[j] = __float2bfloat16((acc[i][j] + bb[j]) * osc);
        *(uint4*)&outp[(size_t)r * DH + tx * 8] = *(const uint4*)t8;
    }
}

// ===========================================================================
// Kernel 2: H -> bf16
// ===========================================================================
__global__ __launch_bounds__(256)
void hconv_kernel(const float* __restrict__ H) {
    size_t i = (size_t)blockIdx.x * 256 + threadIdx.x;
    float4 v = ((const float4*)H)[i];
    __nv_bfloat162 a = __floats2bfloat162_rn(v.x, v.y);
    __nv_bfloat162 b = __floats2bfloat162_rn(v.z, v.w);
    uint2 o;
    o.x = *(uint32_t*)&a;
    o.y = *(uint32_t*)&b;
    ((uint2*)g_Hb)[i] = o;
}

// ===========================================================================
// Kernel 3: flash attention, half-tile software pipeline.
// 8 warps: wr = wid>>2 (32 q-rows), wq = wid&3.
// Per 64-key half: MMA1(h) [wq = 16-key slice] interleaved with
// MMA2(h-1) [wq = 64-col slice, 64 keys from P buf (h-1)&1].
// ===========================================================================
__device__ __forceinline__ void issue_tile(uint32_t sb, int tid, int k0, int stage) {
    {
        const char* src = (const char*)(g_Kb + (size_t)k0 * DH);
        uint32_t dstb = sb + OFF_K + stage * KBYTES;
        #pragma unroll
        for (int i = tid; i < 2048; i += 256) {
            int r = i >> 4, c = i & 15;
            cp16(dstb + r * KS_STRIDE + c * 16, src + r * 256 + c * 16);
        }
    }
    {
        const char* src = (const char*)(g_Hb + (size_t)k0 * TT);
        uint32_t dstb = sb + OFF_H + stage * HBYTES;
        #pragma unroll
        for (int i = tid; i < 4096; i += 256) {
            int r = i >> 5, c = i & 31;
            cp16(dstb + r * HS_STRIDE + c * 16, src + r * 512 + c * 16);
        }
    }
}

struct WarpCtx {
    int wr, wq, g, t;
    int nrow16;         // MMA1 B key-row comp within 16-key slice
    int kc;             // MMA1 B k offset
    int am, akc;        // MMA2 A (P) row/k comps
    int bk, bn;         // MMA2 B (H) row/col comps
};

// MMA1: S[32, 16-key slice] over half at key offset koff within the K tile
__device__ __forceinline__ void mma1_half(uint32_t kbase, int koff,
                                          const uint32_t aq[2][8][4],
                                          float sacc[2][2][4], const WarpCtx& w) {
    #pragma unroll
    for (int mb = 0; mb < 2; mb++)
        #pragma unroll
        for (int nb = 0; nb < 2; nb++)
            #pragma unroll
            for (int x = 0; x < 4; x++) sacc[mb][nb][x] = 0.f;
    #pragma unroll
    for (int s = 0; s < 8; s++) {
        uint32_t addr = kbase + (koff + w.nrow16) * KS_STRIDE + s * 32 + w.kc;
        uint32_t b0, b1, b2, b3;
        ldsm_x4(b0, b1, b2, b3, addr);
        #pragma unroll
        for (int mb = 0; mb < 2; mb++) {
            mma16816(sacc[mb][0], aq[mb][s], b0, b1);
            mma16816(sacc[mb][1], aq[mb][s], b2, b3);
        }
    }
}

// MMA2: O[32, 64-col slice] += P[32, 64 keys] @ H[64 keys, 64-col slice]
__device__ __forceinline__ void mma2_half(uint32_t pb, uint32_t hb, int koff,
                                          float oacc[16][4], const WarpCtx& w) {
    #pragma unroll
    for (int s2 = 0; s2 < 4; s2++) {
        uint32_t pa[2][4];
        #pragma unroll
        for (int mb = 0; mb < 2; mb++) {
            uint32_t addr = pb + (w.wr * 32 + mb * 16 + w.am) * PB_STRIDE
                          + s2 * 32 + w.akc;
            ldsm_x4(pa[mb][0], pa[mb][1], pa[mb][2], pa[mb][3], addr);
        }
        const int krow = koff + s2 * 16 + w.bk;
        #pragma unroll
        for (int jj = 0; jj < 4; jj++) {
            uint32_t addr = hb + krow * HS_STRIDE + (w.wq * 64 + jj * 16 + w.bn) * 2;
            uint32_t b0, b1, b2, b3;
            ldsm_x4_t(b0, b1, b2, b3, addr);
            #pragma unroll
            for (int mb = 0; mb < 2; mb++) {
                mma16816(oacc[mb * 8 + jj * 2],     pa[mb], b0, b1);
                mma16816(oacc[mb * 8 + jj * 2 + 1], pa[mb], b2, b3);
            }
        }
    }
}

// exp + diag + row sums + STS P into buf
__device__ __forceinline__ void exp_half(char* sm, uint32_t pbw, int h, int q0,
                                         float sacc[2][2][4], float lsum[4],
                                         const WarpCtx& w) {
    const int diag_h = q0 >> 6;
    const bool dt = (h == diag_h);
    #pragma unroll
    for (int mb = 0; mb < 2; mb++) {
        const int row0 = w.wr * 32 + mb * 16 + w.g;
        const int grow0 = q0 + row0, grow1 = grow0 + 8;
        #pragma unroll
        for (int jj = 0; jj < 2; jj++) {
            int col = w.wq * 16 + jj * 8 + 2 * w.t;    // 0..63 within half
            int gcol = h * 64 + col;
            float p0 = ex2f(sacc[mb][jj][0]);
            float p1 = ex2f(sacc[mb][jj][1]);
            float p2 = ex2f(sacc[mb][jj][2]);
            float p3 = ex2f(sacc[mb][jj][3]);
            if (dt) {   // diagonal logit forced to 0 -> p = 1
                if (grow0 == gcol)     p0 = 1.f;
                if (grow0 == gcol + 1) p1 = 1.f;
                if (grow1 == gcol)     p2 = 1.f;
                if (grow1 == gcol + 1) p3 = 1.f;
            }
            lsum[2 * mb]     += p0 + p1;
            lsum[2 * mb + 1] += p2 + p3;
            *(uint32_t*)(sm + pbw + row0 * PB_STRIDE + col * 2) = packbf2(p0, p1);
            *(uint32_t*)(sm + pbw + (row0 + 8) * PB_STRIDE + col * 2) = packbf2(p2, p3);
        }
    }
}

__global__ __launch_bounds__(256, 1)
void attn9_kernel(const float* __restrict__ H, float* __restrict__ out) {
    extern __shared__ char sm[];
    const uint32_t sb = smem_u32(sm);
    const int tid = threadIdx.x;
    const int wid = tid >> 5, lane = tid & 31;
    const int q0 = blockIdx.x * BM;
    const int g = lane >> 2, t = lane & 3;
    const int bl = lane >> 3, rl = lane & 7;

    WarpCtx w;
    w.wr = wid >> 2; w.wq = wid & 3; w.g = g; w.t = t;
    w.nrow16 = w.wq * 16 + rl + ((bl & 2) ? 8 : 0);
    w.kc  = (bl & 1) ? 16 : 0;
    w.am  = rl + ((bl & 1) ? 8 : 0);
    w.akc = (bl & 2) ? 16 : 0;
    w.bk  = rl + ((bl & 1) ? 8 : 0);
    w.bn  = (bl & 2) ? 8 : 0;

    // prefetch tile 0
    issue_tile(sb, tid, 0, 0);
    cp_commit();

    // stage Q (prologue aliasing of the P-buffer region)
    for (int i = tid; i < BM * 16; i += 256) {
        int r = i >> 4, c = i & 15;
        uint4 v = *(const uint4*)(g_Qb + (size_t)(q0 + r) * DH + c * 8);
        *(uint4*)(sm + OFF_P + r * PS_STRIDE + c * 16) = v;
    }
    __syncthreads();

    uint32_t aq[2][8][4];
    #pragma unroll
    for (int mb = 0; mb < 2; mb++) {
        int m = w.wr * 32 + mb * 16 + rl + ((bl & 1) ? 8 : 0);
        #pragma unroll
        for (int s = 0; s < 8; s++) {
            uint32_t addr = sb + OFF_P + m * PS_STRIDE + s * 32 + ((bl & 2) ? 16 : 0);
            ldsm_x4(aq[mb][s][0], aq[mb][s][1], aq[mb][s][2], aq[mb][s][3], addr);
        }
    }
    __syncthreads();   // Q reads done before P bufs overwrite the region

    float oacc[16][4];
    #pragma unroll
    for (int i = 0; i < 16; i++)
        #pragma unroll
        for (int j = 0; j < 4; j++) oacc[i][j] = 0.f;
    float lsum[4] = {0.f, 0.f, 0.f, 0.f};
    float sacc[2][2][4];

    for (int kt = 0; kt < NT; kt++) {
        const int cur = kt & 1;
        const uint32_t kbase = sb + OFF_K + cur * KBYTES;
        const uint32_t hcur  = sb + OFF_H + cur * HBYTES;
        const uint32_t hold  = sb + OFF_H + (cur ^ 1) * HBYTES;

        // ===== even half h0 = 2kt =====
        cp_wait0();
        __syncthreads();   // tile kt ready; P(h1 of kt-1) visible; old-H reads fencing below

        mma1_half(kbase, 0, aq, sacc, w);
        if (kt > 0)
            mma2_half(sb + OFF_P + PBUF, hold, 64, oacc, w);   // h-1 = odd half of kt-1
        exp_half(sm, OFF_P, 2 * kt, q0, sacc, lsum, w);        // P -> buf 0

        __syncthreads();   // P(h0) visible; all old-H-stage reads drained

        // ===== odd half h1 = 2kt+1 =====
        if (kt + 1 < NT) {
            issue_tile(sb, tid, (kt + 1) * BN, cur ^ 1);       // overwrites old stage
            cp_commit();
        }
        mma1_half(kbase, 64, aq, sacc, w);
        mma2_half(sb + OFF_P, hcur, 0, oacc, w);               // h-1 = even half, buf 0
        exp_half(sm, OFF_P + PBUF, 2 * kt + 1, q0, sacc, lsum, w);  // P -> buf 1
        // loop-top sync provides P(h1) visibility
    }

    // drain: MMA2 for the last half (odd half of tile NT-1, stage (NT-1)&1)
    __syncthreads();
    mma2_half(sb + OFF_P + PBUF, sb + OFF_H + ((NT - 1) & 1) * HBYTES, 64, oacc, w);

    // ---- epilogue ----
    #pragma unroll
    for (int i = 0; i < 4; i++) {
        lsum[i] += __shfl_xor_sync(0xffffffffu, lsum[i], 1);
        lsum[i] += __shfl_xor_sync(0xffffffffu, lsum[i], 2);
    }
    float* Ls = (float*)(sm + OFF_L);
    if (t == 0) {
        int r = w.wr * 32 + g;
        Ls[w.wq * 64 + r]      = lsum[0];
        Ls[w.wq * 64 + r + 8]  = lsum[1];
        Ls[w.wq * 64 + r + 16] = lsum[2];
        Ls[w.wq * 64 + r + 24] = lsum[3];
    }
    __syncthreads();

    #pragma unroll
    for (int mb = 0; mb < 2; mb++) {
        int row0 = w.wr * 32 + mb * 16 + g;
        float invA = 1.f / (Ls[row0] + Ls[64 + row0] + Ls[128 + row0] + Ls[192 + row0]);
        float invB = 1.f / (Ls[row0 + 8] + Ls[64 + row0 + 8] +
                            Ls[128 + row0 + 8] + Ls[192 + row0 + 8]);
        int grow0 = q0 + row0;
        #pragma unroll
        for (int jj = 0; jj < 4; jj++) {
            #pragma unroll
            for (int n8 = 0; n8 < 2; n8++) {
                int col = w.wq * 64 + jj * 16 + n8 * 8 + 2 * t;
                const float* oa = oacc[mb * 8 + jj * 2 + n8];
                float2 h0 = *(const float2*)(H + (size_t)grow0 * TT + col);
                float2 h1 = *(const float2*)(H + (size_t)(grow0 + 8) * TT + col);
                float2 o0, o1;
                o0.x = oa[0] * invA + h0.x;
                o0.y = oa[1] * invA + h0.y;
                o1.x = oa[2] * invB + h1.x;
                o1.y = oa[3] * invB + h1.y;
                *(float2*)(out + (size_t)grow0 * TT + col) = o0;
                *(float2*)(out + (size_t)(grow0 + 8) * TT + col) = o1;
            }
        }
    }
}

// ===========================================================================
extern "C" void kernel_launch(void* const* d_in, const int* in_sizes, int n_in,
                              void* d_out, int out_size) {
    const float* H  = (const float*)d_in[0];
    const float* Wq = (const float*)d_in[1];
    const float* bq = (const float*)d_in[2];
    const float* Wk = (const float*)d_in[3];
    const float* bk = (const float*)d_in[4];
    float* out = (float*)d_out;

    cudaFuncSetAttribute(attn9_kernel,
                         cudaFuncAttributeMaxDynamicSharedMemorySize, ATTN_SMEM);

    qk_kernel<<<dim3(NN / 128, 2), 256>>>(H, Wq, bq, Wk, bk);
    hconv_kernel<<<(NN * TT / 4) / 256, 256>>>(H);
    attn9_kernel<<<NN / BM, 256, ATTN_SMEM>>>(H, out);
}